// round 15
// baseline (speedup 1.0000x reference)
#include <cuda_runtime.h>
#include <cuda_bf16.h>
#include <math.h>

// Problem constants
#define BB   32
#define INF  128
#define HH   1024
#define OUTF 128
#define KCAT (INF + HH)   // 1152
#define TPB  256
#define RPB  8            // rows (warps) per block
#define NCH  3            // chains: 11 / 11 / 10 batches

// Scratch (allocation-free rule: __device__ globals)
__device__ float g_c0[BB * HH];
__device__ float g_c1[BB * HH];
__device__ float g_c2[BB * HH];
__device__ float g_logits[BB * OUTF];

// 256-bit streaming global load (sm_100+/PTX 8.8): 8 floats, .cs evict-first.
__device__ __forceinline__ void ldg_cs_v8(const float* p, float4& a, float4& b) {
    asm volatile("ld.global.cs.v8.f32 {%0,%1,%2,%3,%4,%5,%6,%7}, [%8];"
        : "=f"(a.x), "=f"(a.y), "=f"(a.z), "=f"(a.w),
          "=f"(b.x), "=f"(b.y), "=f"(b.z), "=f"(b.w)
        : "l"(p));
}

// ---------------------------------------------------------------------------
// R12-proven matvec tile kernel, W loads upgraded to 256-bit LDG.
// 8 warps/block = 8 consecutive rows of ONE batch; activation staged in smem.
// v8 lane layout: iteration j covers floats [j*256, j*256+256), lane owns
// floats j*256 + lane*8 .. +8  (32B-aligned).
// ---------------------------------------------------------------------------
template <int K, bool LAYER0>
__global__ __launch_bounds__(TPB) void matvec_kernel(
    const float* __restrict__ W, const float* __restrict__ bias,
    const float* __restrict__ in0,   // LAYER0: x ; else: activations [B,K]
    const float* __restrict__ in1,   // LAYER0: hidden ; else unused
    float* __restrict__ out, int Hout, int row_off)
{
    __shared__ float4 xs[K / 4];

    const int rowbase = row_off + blockIdx.x * RPB;
    const int b = rowbase / Hout;

    if (LAYER0) {
        const float4* xv = reinterpret_cast<const float4*>(in0 + (size_t)b * INF);
        const float4* hv = reinterpret_cast<const float4*>(in1 + (size_t)b * HH);
#pragma unroll
        for (int i = threadIdx.x; i < K / 4; i += TPB)
            xs[i] = (i < INF / 4) ? xv[i] : hv[i - INF / 4];
    } else {
        const float4* src = reinterpret_cast<const float4*>(in0 + (size_t)b * K);
#pragma unroll
        for (int i = threadIdx.x; i < K / 4; i += TPB)
            xs[i] = src[i];
    }
    __syncthreads();

    const int warp = threadIdx.x >> 5;
    const int lane = threadIdx.x & 31;
    const int row  = rowbase + warp;
    const int o    = row - b * Hout;

    const float* __restrict__ Wrow = W + (size_t)row * K;
    constexpr int NV8 = K / 256;        // full 256-float iterations (4 for both K)
    constexpr int REM = K - NV8 * 256;  // 0 (HH) or 128 (KCAT)

    // Front-batch all W loads: NV8 v8 loads (+1 float4 for the KCAT remainder).
    float4 w[2 * NV8 + (REM ? 1 : 0)];
#pragma unroll
    for (int j = 0; j < NV8; j++)
        ldg_cs_v8(Wrow + j * 256 + lane * 8, w[2 * j], w[2 * j + 1]);
    if (REM)
        w[2 * NV8] = __ldcs(reinterpret_cast<const float4*>(Wrow) + NV8 * 64 + lane);

    float sum = 0.f;
#pragma unroll
    for (int j = 0; j < NV8; j++) {
        float4 v0 = xs[j * 64 + lane * 2];
        float4 v1 = xs[j * 64 + lane * 2 + 1];
        float4 a = w[2 * j], c = w[2 * j + 1];
        sum += a.x * v0.x + a.y * v0.y + a.z * v0.z + a.w * v0.w;
        sum += c.x * v1.x + c.y * v1.y + c.z * v1.z + c.w * v1.w;
    }
    if (REM) {
        float4 v = xs[NV8 * 64 + lane];
        float4 a = w[2 * NV8];
        sum += a.x * v.x + a.y * v.y + a.z * v.z + a.w * v.w;
    }
#pragma unroll
    for (int off = 16; off; off >>= 1)
        sum += __shfl_xor_sync(0xFFFFFFFFu, sum, off);

    if (lane == 0)
        out[row] = tanhf(sum + bias[o]);
}

// Fused heads (runtime batch count): blocks [0,NBH) -> Wh tiles (tanh),
// blocks [NBH, ...) -> Wo tiles (logits, no tanh). v8 W loads.
__global__ __launch_bounds__(TPB) void heads_kernel(
    const float* __restrict__ Wh, const float* __restrict__ bh,
    const float* __restrict__ Wo, const float* __restrict__ bo,
    float* __restrict__ new_hidden_out, int boff, int nbatch)
{
    __shared__ float4 xs[HH / 4];

    const int NBH = (nbatch * HH) / RPB;
    const bool is_h = ((int)blockIdx.x < NBH);
    int rowbase, b, Hout;
    const float* Wbase; const float* bias;
    if (is_h) { rowbase = boff * HH   + blockIdx.x * RPB;         Hout = HH;   Wbase = Wh; bias = bh; }
    else      { rowbase = boff * OUTF + (blockIdx.x - NBH) * RPB; Hout = OUTF; Wbase = Wo; bias = bo; }
    b = rowbase / Hout;

    {
        const float4* src = reinterpret_cast<const float4*>(g_c2 + (size_t)b * HH);
#pragma unroll
        for (int i = threadIdx.x; i < HH / 4; i += TPB)
            xs[i] = src[i];
    }
    __syncthreads();

    const int warp = threadIdx.x >> 5;
    const int lane = threadIdx.x & 31;
    const int row  = rowbase + warp;
    const int o    = row - b * Hout;

    const float* __restrict__ Wrow = Wbase + (size_t)row * HH;
    constexpr int NV8 = HH / 256;   // 4

    float4 w[2 * NV8];
#pragma unroll
    for (int j = 0; j < NV8; j++)
        ldg_cs_v8(Wrow + j * 256 + lane * 8, w[2 * j], w[2 * j + 1]);

    float sum = 0.f;
#pragma unroll
    for (int j = 0; j < NV8; j++) {
        float4 v0 = xs[j * 64 + lane * 2];
        float4 v1 = xs[j * 64 + lane * 2 + 1];
        float4 a = w[2 * j], c = w[2 * j + 1];
        sum += a.x * v0.x + a.y * v0.y + a.z * v0.z + a.w * v0.w;
        sum += c.x * v1.x + c.y * v1.y + c.z * v1.z + c.w * v1.w;
    }
#pragma unroll
    for (int off = 16; off; off >>= 1)
        sum += __shfl_xor_sync(0xFFFFFFFFu, sum, off);

    if (lane == 0) {
        if (is_h) new_hidden_out[row] = tanhf(sum + bias[o]);
        else      g_logits[row] = sum + bias[o];
    }
}

// log_softmax for batches [boff, boff+nwarps); one warp per batch.
__global__ void log_softmax_kernel(float* __restrict__ out, int boff) {
    const int warp = threadIdx.x >> 5;
    const int lane = threadIdx.x & 31;
    const int bq = boff + warp;
    const float* l = g_logits + bq * OUTF;

    float v[4];
#pragma unroll
    for (int i = 0; i < 4; i++) v[i] = l[i * 32 + lane];

    float m = fmaxf(fmaxf(v[0], v[1]), fmaxf(v[2], v[3]));
#pragma unroll
    for (int off = 16; off; off >>= 1)
        m = fmaxf(m, __shfl_xor_sync(0xFFFFFFFFu, m, off));

    float s = 0.f;
#pragma unroll
    for (int i = 0; i < 4; i++) s += __expf(v[i] - m);
#pragma unroll
    for (int off = 16; off; off >>= 1)
        s += __shfl_xor_sync(0xFFFFFFFFu, s, off);

    float lse = m + logf(s);
#pragma unroll
    for (int i = 0; i < 4; i++)
        out[bq * OUTF + i * 32 + lane] = v[i] - lse;
}

extern "C" void kernel_launch(void* const* d_in, const int* in_sizes, int n_in,
                              void* d_out, int out_size) {
    const float* x      = (const float*)d_in[0];
    const float* hidden = (const float*)d_in[1];
    const float* W0 = (const float*)d_in[2];
    const float* b0 = (const float*)d_in[3];
    const float* W1 = (const float*)d_in[4];
    const float* b1 = (const float*)d_in[5];
    const float* W2 = (const float*)d_in[6];
    const float* b2 = (const float*)d_in[7];
    const float* Wh = (const float*)d_in[8];
    const float* bh = (const float*)d_in[9];
    const float* Wo = (const float*)d_in[10];
    const float* bo = (const float*)d_in[11];

    float* out = (float*)d_out;                 // [B*OUT] log_softmax, then [B*H] new_hidden
    float* new_hidden = out + BB * OUTF;

    float *c0, *c1, *c2;
    cudaGetSymbolAddress((void**)&c0, g_c0);
    cudaGetSymbolAddress((void**)&c1, g_c1);
    cudaGetSymbolAddress((void**)&c2, g_c2);

    // Two side streams + fork/join events (R12-proven pattern).
    static cudaStream_t st[NCH - 1] = {};
    static cudaEvent_t evFork = nullptr, evJoin[NCH - 1] = {};
    if (!st[0]) {
        for (int i = 0; i < NCH - 1; i++) {
            cudaStreamCreateWithFlags(&st[i], cudaStreamNonBlocking);
            cudaEventCreateWithFlags(&evJoin[i], cudaEventDisableTiming);
        }
        cudaEventCreateWithFlags(&evFork, cudaEventDisableTiming);
    }

    // Chain batch partitions: 11 / 11 / 10
    const int nbat[NCH] = {11, 11, 10};
    const int boff[NCH] = {0, 11, 22};

    // Fork side chains off the capture (default) stream.
    cudaEventRecord(evFork, 0);
    for (int i = 0; i < NCH - 1; i++)
        cudaStreamWaitEvent(st[i], evFork, 0);

    for (int ch = 0; ch < NCH; ch++) {
        cudaStream_t s = (ch == 0) ? (cudaStream_t)0 : st[ch - 1];
        const int nb = nbat[ch];
        const int bo_ = boff[ch];
        const int roff = bo_ * HH;
        const int blksL = (nb * HH) / RPB;
        const int blksH = blksL + (nb * OUTF) / RPB;

        matvec_kernel<KCAT, true ><<<blksL, TPB, 0, s>>>(W0, b0, x,  hidden,  c0, HH, roff);
        matvec_kernel<HH,   false><<<blksL, TPB, 0, s>>>(W1, b1, c0, nullptr, c1, HH, roff);
        matvec_kernel<HH,   false><<<blksL, TPB, 0, s>>>(W2, b2, c1, nullptr, c2, HH, roff);
        heads_kernel<<<blksH, TPB, 0, s>>>(Wh, bh, Wo, bo, new_hidden, bo_, nb);
        log_softmax_kernel<<<1, nb * 32, 0, s>>>(out, bo_);
    }

    // Join side chains back to the capture stream.
    for (int i = 0; i < NCH - 1; i++) {
        cudaEventRecord(evJoin[i], st[i]);
        cudaStreamWaitEvent(0, evJoin[i], 0);
    }

    (void)in_sizes; (void)n_in; (void)out_size;
}

// round 16
// speedup vs baseline: 1.0244x; 1.0244x over previous
#include <cuda_runtime.h>
#include <cuda_bf16.h>
#include <math.h>

// Problem constants
#define BB   32
#define INF  128
#define HH   1024
#define OUTF 128
#define KCAT (INF + HH)   // 1152
#define TPB  256
#define RPB  8            // rows (warps) per block
#define NCH  3            // chains: 11 / 11 / 10 batches

// Scratch (allocation-free rule: __device__ globals)
__device__ float g_c0[BB * HH];
__device__ float g_c1[BB * HH];
__device__ float g_c2[BB * HH];
__device__ float g_logits[BB * OUTF];

// ---------------------------------------------------------------------------
// R2/R7-proven matvec tile kernel: 8 warps/block = 8 consecutive rows of ONE
// batch; activation staged in smem once; W front-batched with __ldcs; tanh.
// ---------------------------------------------------------------------------
template <int K, bool LAYER0>
__global__ __launch_bounds__(TPB) void matvec_kernel(
    const float* __restrict__ W, const float* __restrict__ bias,
    const float* __restrict__ in0,   // LAYER0: x ; else: activations [B,K]
    const float* __restrict__ in1,   // LAYER0: hidden ; else unused
    float* __restrict__ out, int Hout, int row_off)
{
    __shared__ float4 xs[K / 4];

    const int rowbase = row_off + blockIdx.x * RPB;
    const int b = rowbase / Hout;

    if (LAYER0) {
        const float4* xv = reinterpret_cast<const float4*>(in0 + (size_t)b * INF);
        const float4* hv = reinterpret_cast<const float4*>(in1 + (size_t)b * HH);
#pragma unroll
        for (int i = threadIdx.x; i < K / 4; i += TPB)
            xs[i] = (i < INF / 4) ? xv[i] : hv[i - INF / 4];
    } else {
        const float4* src = reinterpret_cast<const float4*>(in0 + (size_t)b * K);
#pragma unroll
        for (int i = threadIdx.x; i < K / 4; i += TPB)
            xs[i] = src[i];
    }
    __syncthreads();

    const int warp = threadIdx.x >> 5;
    const int lane = threadIdx.x & 31;
    const int row  = rowbase + warp;
    const int o    = row - b * Hout;

    const float4* __restrict__ Wr = reinterpret_cast<const float4*>(W + (size_t)row * K);
    constexpr int NIT = K / 128;

    float4 w[NIT];
#pragma unroll
    for (int j = 0; j < NIT; j++)
        w[j] = __ldcs(Wr + j * 32 + lane);

    float sum = 0.f;
#pragma unroll
    for (int j = 0; j < NIT; j++) {
        float4 v = xs[j * 32 + lane];
        sum += w[j].x * v.x + w[j].y * v.y + w[j].z * v.z + w[j].w * v.w;
    }
#pragma unroll
    for (int off = 16; off; off >>= 1)
        sum += __shfl_xor_sync(0xFFFFFFFFu, sum, off);

    if (lane == 0)
        out[row] = tanhf(sum + bias[o]);
}

// Fused heads (runtime batch count): blocks [0,NBH) -> Wh tiles (tanh),
// blocks [NBH, ...) -> Wo tiles (logits, no tanh).
__global__ __launch_bounds__(TPB) void heads_kernel(
    const float* __restrict__ Wh, const float* __restrict__ bh,
    const float* __restrict__ Wo, const float* __restrict__ bo,
    float* __restrict__ new_hidden_out, int boff, int nbatch)
{
    __shared__ float4 xs[HH / 4];

    const int NBH = (nbatch * HH) / RPB;
    const bool is_h = ((int)blockIdx.x < NBH);
    int rowbase, b, Hout;
    const float* Wbase; const float* bias;
    if (is_h) { rowbase = boff * HH   + blockIdx.x * RPB;         Hout = HH;   Wbase = Wh; bias = bh; }
    else      { rowbase = boff * OUTF + (blockIdx.x - NBH) * RPB; Hout = OUTF; Wbase = Wo; bias = bo; }
    b = rowbase / Hout;

    {
        const float4* src = reinterpret_cast<const float4*>(g_c2 + (size_t)b * HH);
#pragma unroll
        for (int i = threadIdx.x; i < HH / 4; i += TPB)
            xs[i] = src[i];
    }
    __syncthreads();

    const int warp = threadIdx.x >> 5;
    const int lane = threadIdx.x & 31;
    const int row  = rowbase + warp;
    const int o    = row - b * Hout;

    const float4* __restrict__ Wr = reinterpret_cast<const float4*>(Wbase + (size_t)row * HH);
    constexpr int NIT = HH / 128;

    float4 w[NIT];
#pragma unroll
    for (int j = 0; j < NIT; j++)
        w[j] = __ldcs(Wr + j * 32 + lane);

    float sum = 0.f;
#pragma unroll
    for (int j = 0; j < NIT; j++) {
        float4 v = xs[j * 32 + lane];
        sum += w[j].x * v.x + w[j].y * v.y + w[j].z * v.z + w[j].w * v.w;
    }
#pragma unroll
    for (int off = 16; off; off >>= 1)
        sum += __shfl_xor_sync(0xFFFFFFFFu, sum, off);

    if (lane == 0) {
        if (is_h) new_hidden_out[row] = tanhf(sum + bias[o]);
        else      g_logits[row] = sum + bias[o];
    }
}

// log_softmax for batches [boff, boff+nwarps); one warp per batch.
__global__ void log_softmax_kernel(float* __restrict__ out, int boff) {
    const int warp = threadIdx.x >> 5;
    const int lane = threadIdx.x & 31;
    const int bq = boff + warp;
    const float* l = g_logits + bq * OUTF;

    float v[4];
#pragma unroll
    for (int i = 0; i < 4; i++) v[i] = l[i * 32 + lane];

    float m = fmaxf(fmaxf(v[0], v[1]), fmaxf(v[2], v[3]));
#pragma unroll
    for (int off = 16; off; off >>= 1)
        m = fmaxf(m, __shfl_xor_sync(0xFFFFFFFFu, m, off));

    float s = 0.f;
#pragma unroll
    for (int i = 0; i < 4; i++) s += __expf(v[i] - m);
#pragma unroll
    for (int off = 16; off; off >>= 1)
        s += __shfl_xor_sync(0xFFFFFFFFu, s, off);

    float lse = m + logf(s);
#pragma unroll
    for (int i = 0; i < 4; i++)
        out[bq * OUTF + i * 32 + lane] = v[i] - lse;
}

extern "C" void kernel_launch(void* const* d_in, const int* in_sizes, int n_in,
                              void* d_out, int out_size) {
    const float* x      = (const float*)d_in[0];
    const float* hidden = (const float*)d_in[1];
    const float* W0 = (const float*)d_in[2];
    const float* b0 = (const float*)d_in[3];
    const float* W1 = (const float*)d_in[4];
    const float* b1 = (const float*)d_in[5];
    const float* W2 = (const float*)d_in[6];
    const float* b2 = (const float*)d_in[7];
    const float* Wh = (const float*)d_in[8];
    const float* bh = (const float*)d_in[9];
    const float* Wo = (const float*)d_in[10];
    const float* bo = (const float*)d_in[11];

    float* out = (float*)d_out;                 // [B*OUT] log_softmax, then [B*H] new_hidden
    float* new_hidden = out + BB * OUTF;

    float *c0, *c1, *c2;
    cudaGetSymbolAddress((void**)&c0, g_c0);
    cudaGetSymbolAddress((void**)&c1, g_c1);
    cudaGetSymbolAddress((void**)&c2, g_c2);

    // Two side streams + fork/join events (R12-proven pattern).
    static cudaStream_t st[NCH - 1] = {};
    static cudaEvent_t evFork = nullptr, evJoin[NCH - 1] = {};
    if (!st[0]) {
        for (int i = 0; i < NCH - 1; i++) {
            cudaStreamCreateWithFlags(&st[i], cudaStreamNonBlocking);
            cudaEventCreateWithFlags(&evJoin[i], cudaEventDisableTiming);
        }
        cudaEventCreateWithFlags(&evFork, cudaEventDisableTiming);
    }

    // Chain batch partitions: 11 / 11 / 10
    const int nbat[NCH] = {11, 11, 10};
    const int boff[NCH] = {0, 11, 22};

    // Fork side chains off the capture (default) stream.
    cudaEventRecord(evFork, 0);
    for (int i = 0; i < NCH - 1; i++)
        cudaStreamWaitEvent(st[i], evFork, 0);

    for (int ch = 0; ch < NCH; ch++) {
        cudaStream_t s = (ch == 0) ? (cudaStream_t)0 : st[ch - 1];
        const int nb = nbat[ch];
        const int bo_ = boff[ch];
        const int roff = bo_ * HH;
        const int blksL = (nb * HH) / RPB;
        const int blksH = blksL + (nb * OUTF) / RPB;

        matvec_kernel<KCAT, true ><<<blksL, TPB, 0, s>>>(W0, b0, x,  hidden,  c0, HH, roff);
        matvec_kernel<HH,   false><<<blksL, TPB, 0, s>>>(W1, b1, c0, nullptr, c1, HH, roff);
        matvec_kernel<HH,   false><<<blksL, TPB, 0, s>>>(W2, b2, c1, nullptr, c2, HH, roff);
        heads_kernel<<<blksH, TPB, 0, s>>>(Wh, bh, Wo, bo, new_hidden, bo_, nb);
        log_softmax_kernel<<<1, nb * 32, 0, s>>>(out, bo_);
    }

    // Join side chains back to the capture stream.
    for (int i = 0; i < NCH - 1; i++) {
        cudaEventRecord(evJoin[i], st[i]);
        cudaStreamWaitEvent(0, evJoin[i], 0);
    }

    (void)in_sizes; (void)n_in; (void)out_size;
}

// round 17
// speedup vs baseline: 1.0400x; 1.0152x over previous
#include <cuda_runtime.h>
#include <cuda_bf16.h>
#include <math.h>

// Problem constants
#define BB   32
#define INF  128
#define HH   1024
#define OUTF 128
#define KCAT (INF + HH)   // 1152
#define TPB  256
#define RPB  8            // rows (warps) per block
#define NCH  3            // chains: 11 / 11 / 10 batches

// Scratch (allocation-free rule: __device__ globals)
__device__ float g_c0[BB * HH];
__device__ float g_c1[BB * HH];
__device__ float g_c2[BB * HH];
__device__ float g_logits[BB * OUTF];

// ---------------------------------------------------------------------------
// R2/R7-proven matvec tile kernel: 8 warps/block = 8 consecutive rows of ONE
// batch; activation staged in smem once; W front-batched with __ldcs; tanh.
// ---------------------------------------------------------------------------
template <int K, bool LAYER0>
__global__ __launch_bounds__(TPB) void matvec_kernel(
    const float* __restrict__ W, const float* __restrict__ bias,
    const float* __restrict__ in0,   // LAYER0: x ; else: activations [B,K]
    const float* __restrict__ in1,   // LAYER0: hidden ; else unused
    float* __restrict__ out, int Hout, int row_off)
{
    __shared__ float4 xs[K / 4];

    const int rowbase = row_off + blockIdx.x * RPB;
    const int b = rowbase / Hout;

    if (LAYER0) {
        const float4* xv = reinterpret_cast<const float4*>(in0 + (size_t)b * INF);
        const float4* hv = reinterpret_cast<const float4*>(in1 + (size_t)b * HH);
#pragma unroll
        for (int i = threadIdx.x; i < K / 4; i += TPB)
            xs[i] = (i < INF / 4) ? xv[i] : hv[i - INF / 4];
    } else {
        const float4* src = reinterpret_cast<const float4*>(in0 + (size_t)b * K);
#pragma unroll
        for (int i = threadIdx.x; i < K / 4; i += TPB)
            xs[i] = src[i];
    }
    __syncthreads();

    const int warp = threadIdx.x >> 5;
    const int lane = threadIdx.x & 31;
    const int row  = rowbase + warp;
    const int o    = row - b * Hout;

    const float4* __restrict__ Wr = reinterpret_cast<const float4*>(W + (size_t)row * K);
    constexpr int NIT = K / 128;

    float4 w[NIT];
#pragma unroll
    for (int j = 0; j < NIT; j++)
        w[j] = __ldcs(Wr + j * 32 + lane);

    float sum = 0.f;
#pragma unroll
    for (int j = 0; j < NIT; j++) {
        float4 v = xs[j * 32 + lane];
        sum += w[j].x * v.x + w[j].y * v.y + w[j].z * v.z + w[j].w * v.w;
    }
#pragma unroll
    for (int off = 16; off; off >>= 1)
        sum += __shfl_xor_sync(0xFFFFFFFFu, sum, off);

    if (lane == 0)
        out[row] = tanhf(sum + bias[o]);
}

// Fused heads (runtime batch count): blocks [0,NBH) -> Wh tiles (tanh),
// blocks [NBH, ...) -> Wo tiles (logits, no tanh).
__global__ __launch_bounds__(TPB) void heads_kernel(
    const float* __restrict__ Wh, const float* __restrict__ bh,
    const float* __restrict__ Wo, const float* __restrict__ bo,
    float* __restrict__ new_hidden_out, int boff, int nbatch)
{
    __shared__ float4 xs[HH / 4];

    const int NBH = (nbatch * HH) / RPB;
    const bool is_h = ((int)blockIdx.x < NBH);
    int rowbase, b, Hout;
    const float* Wbase; const float* bias;
    if (is_h) { rowbase = boff * HH   + blockIdx.x * RPB;         Hout = HH;   Wbase = Wh; bias = bh; }
    else      { rowbase = boff * OUTF + (blockIdx.x - NBH) * RPB; Hout = OUTF; Wbase = Wo; bias = bo; }
    b = rowbase / Hout;

    {
        const float4* src = reinterpret_cast<const float4*>(g_c2 + (size_t)b * HH);
#pragma unroll
        for (int i = threadIdx.x; i < HH / 4; i += TPB)
            xs[i] = src[i];
    }
    __syncthreads();

    const int warp = threadIdx.x >> 5;
    const int lane = threadIdx.x & 31;
    const int row  = rowbase + warp;
    const int o    = row - b * Hout;

    const float4* __restrict__ Wr = reinterpret_cast<const float4*>(Wbase + (size_t)row * HH);
    constexpr int NIT = HH / 128;

    float4 w[NIT];
#pragma unroll
    for (int j = 0; j < NIT; j++)
        w[j] = __ldcs(Wr + j * 32 + lane);

    float sum = 0.f;
#pragma unroll
    for (int j = 0; j < NIT; j++) {
        float4 v = xs[j * 32 + lane];
        sum += w[j].x * v.x + w[j].y * v.y + w[j].z * v.z + w[j].w * v.w;
    }
#pragma unroll
    for (int off = 16; off; off >>= 1)
        sum += __shfl_xor_sync(0xFFFFFFFFu, sum, off);

    if (lane == 0) {
        if (is_h) new_hidden_out[row] = tanhf(sum + bias[o]);
        else      g_logits[row] = sum + bias[o];
    }
}

// log_softmax for batches [boff, boff+nwarps); one warp per batch.
__global__ void log_softmax_kernel(float* __restrict__ out, int boff) {
    const int warp = threadIdx.x >> 5;
    const int lane = threadIdx.x & 31;
    const int bq = boff + warp;
    const float* l = g_logits + bq * OUTF;

    float v[4];
#pragma unroll
    for (int i = 0; i < 4; i++) v[i] = l[i * 32 + lane];

    float m = fmaxf(fmaxf(v[0], v[1]), fmaxf(v[2], v[3]));
#pragma unroll
    for (int off = 16; off; off >>= 1)
        m = fmaxf(m, __shfl_xor_sync(0xFFFFFFFFu, m, off));

    float s = 0.f;
#pragma unroll
    for (int i = 0; i < 4; i++) s += __expf(v[i] - m);
#pragma unroll
    for (int off = 16; off; off >>= 1)
        s += __shfl_xor_sync(0xFFFFFFFFu, s, off);

    float lse = m + logf(s);
#pragma unroll
    for (int i = 0; i < 4; i++)
        out[bq * OUTF + i * 32 + lane] = v[i] - lse;
}

extern "C" void kernel_launch(void* const* d_in, const int* in_sizes, int n_in,
                              void* d_out, int out_size) {
    const float* x      = (const float*)d_in[0];
    const float* hidden = (const float*)d_in[1];
    const float* W0 = (const float*)d_in[2];
    const float* b0 = (const float*)d_in[3];
    const float* W1 = (const float*)d_in[4];
    const float* b1 = (const float*)d_in[5];
    const float* W2 = (const float*)d_in[6];
    const float* b2 = (const float*)d_in[7];
    const float* Wh = (const float*)d_in[8];
    const float* bh = (const float*)d_in[9];
    const float* Wo = (const float*)d_in[10];
    const float* bo = (const float*)d_in[11];

    float* out = (float*)d_out;                 // [B*OUT] log_softmax, then [B*H] new_hidden
    float* new_hidden = out + BB * OUTF;

    float *c0, *c1, *c2;
    cudaGetSymbolAddress((void**)&c0, g_c0);
    cudaGetSymbolAddress((void**)&c1, g_c1);
    cudaGetSymbolAddress((void**)&c2, g_c2);

    // Two side streams + fork/join events (R12-proven pattern).
    static cudaStream_t st[NCH - 1] = {};
    static cudaEvent_t evFork = nullptr, evJoin[NCH - 1] = {};
    if (!st[0]) {
        for (int i = 0; i < NCH - 1; i++) {
            cudaStreamCreateWithFlags(&st[i], cudaStreamNonBlocking);
            cudaEventCreateWithFlags(&evJoin[i], cudaEventDisableTiming);
        }
        cudaEventCreateWithFlags(&evFork, cudaEventDisableTiming);
    }

    // Chain batch partitions: 11 / 11 / 10
    const int nbat[NCH] = {11, 11, 10};
    const int boff[NCH] = {0, 11, 22};

    // Fork side chains off the capture (default) stream.
    cudaEventRecord(evFork, 0);
    for (int i = 0; i < NCH - 1; i++)
        cudaStreamWaitEvent(st[i], evFork, 0);

    for (int ch = 0; ch < NCH; ch++) {
        cudaStream_t s = (ch == 0) ? (cudaStream_t)0 : st[ch - 1];
        const int nb = nbat[ch];
        const int bo_ = boff[ch];
        const int roff = bo_ * HH;
        const int blksL = (nb * HH) / RPB;
        const int blksH = blksL + (nb * OUTF) / RPB;

        matvec_kernel<KCAT, true ><<<blksL, TPB, 0, s>>>(W0, b0, x,  hidden,  c0, HH, roff);
        matvec_kernel<HH,   false><<<blksL, TPB, 0, s>>>(W1, b1, c0, nullptr, c1, HH, roff);
        matvec_kernel<HH,   false><<<blksL, TPB, 0, s>>>(W2, b2, c1, nullptr, c2, HH, roff);
        heads_kernel<<<blksH, TPB, 0, s>>>(Wh, bh, Wo, bo, new_hidden, bo_, nb);
        log_softmax_kernel<<<1, nb * 32, 0, s>>>(out, bo_);
    }

    // Join side chains back to the capture stream.
    for (int i = 0; i < NCH - 1; i++) {
        cudaEventRecord(evJoin[i], st[i]);
        cudaStreamWaitEvent(0, evJoin[i], 0);
    }

    (void)in_sizes; (void)n_in; (void)out_size;
}